// round 1
// baseline (speedup 1.0000x reference)
#include <cuda_runtime.h>
#include <cstdint>

#define NN   20000
#define BB   128
#define EE   320000
#define FIN  768
#define RAWF 5000
#define HH   256
#define CC   4

// ---------------- scratch (device globals; no allocation allowed) ----------------
__device__ __align__(16) float g_h[NN * HH];        // GEMM output (XW)
__device__ __align__(16) float g_agg[NN * HH];      // aggregated / layer activation
__device__ __align__(16) float g_newxin[BB * 2 * RAWF];
__device__ __align__(16) float g_l1[BB * 512];
__device__ __align__(16) float g_newx[BB * HH];
__device__ __align__(16) float g_xmax[BB * HH];
__device__ __align__(16) float g_p0[BB * HH];
__device__ __align__(16) float g_p1[BB * HH];
__device__ __align__(16) float g_p2[BB * HH];
__device__ int   g_deg[NN];
__device__ float g_dinv[NN];
__device__ int   g_bounds[BB + 1];

// ---------------- segment bounds (batch is sorted) ----------------
__global__ void bounds_kernel(const int* __restrict__ batch) {
    int b = threadIdx.x;
    if (b > BB) return;
    int lo = 0, hi = NN;
    while (lo < hi) {
        int mid = (lo + hi) >> 1;
        if (batch[mid] < b) lo = mid + 1; else hi = mid;
    }
    g_bounds[b] = lo;
}

// ---------------- degree / norm ----------------
__global__ void deg_init_kernel() {
    int i = blockIdx.x * blockDim.x + threadIdx.x;
    if (i < NN) g_deg[i] = 1;   // self loop
}
__global__ void deg_add_kernel(const int* __restrict__ dst) {
    int e = blockIdx.x * blockDim.x + threadIdx.x;
    if (e < EE) atomicAdd(&g_deg[dst[e]], 1);
}
__global__ void dinv_kernel() {
    int i = blockIdx.x * blockDim.x + threadIdx.x;
    if (i < NN) g_dinv[i] = rsqrtf((float)g_deg[i]);
}

// ---------------- SGEMM: C[M,N] = A[M,K] @ B[K,N]  (128x128x8, 8x8/thread) ----------------
__global__ __launch_bounds__(256, 2)
void sgemm128(const float* __restrict__ A, const float* __restrict__ B,
              float* __restrict__ C, int M, int N, int K) {
    __shared__ float As[8][128];
    __shared__ float Bs[8][128];
    int tid = threadIdx.x;
    int tx = tid & 15, ty = tid >> 4;
    int bm = blockIdx.y * 128, bn = blockIdx.x * 128;

    float acc[8][8];
#pragma unroll
    for (int i = 0; i < 8; i++)
#pragma unroll
        for (int j = 0; j < 8; j++) acc[i][j] = 0.f;

    int arow = tid >> 1;            // 0..127
    int acol = (tid & 1) * 4;       // 0 or 4
    int brow = tid >> 5;            // 0..7
    int bcol = (tid & 31) * 4;      // 0..124

    for (int k0 = 0; k0 < K; k0 += 8) {
        float4 av = make_float4(0.f, 0.f, 0.f, 0.f);
        int gr = bm + arow;
        if (gr < M) av = *(const float4*)(A + (size_t)gr * K + k0 + acol);
        As[acol + 0][arow] = av.x;
        As[acol + 1][arow] = av.y;
        As[acol + 2][arow] = av.z;
        As[acol + 3][arow] = av.w;

        float4 bv = make_float4(0.f, 0.f, 0.f, 0.f);
        int gc = bn + bcol;
        if (gc < N) bv = *(const float4*)(B + (size_t)(k0 + brow) * N + gc);
        Bs[brow][bcol + 0] = bv.x;
        Bs[brow][bcol + 1] = bv.y;
        Bs[brow][bcol + 2] = bv.z;
        Bs[brow][bcol + 3] = bv.w;
        __syncthreads();

#pragma unroll
        for (int kk = 0; kk < 8; kk++) {
            float a[8], b[8];
#pragma unroll
            for (int i = 0; i < 8; i++) a[i] = As[kk][ty * 8 + i];
#pragma unroll
            for (int j = 0; j < 8; j++) b[j] = Bs[kk][tx * 8 + j];
#pragma unroll
            for (int i = 0; i < 8; i++)
#pragma unroll
                for (int j = 0; j < 8; j++) acc[i][j] += a[i] * b[j];
        }
        __syncthreads();
    }

#pragma unroll
    for (int i = 0; i < 8; i++) {
        int r = bm + ty * 8 + i;
        if (r >= M) continue;
        int c0 = bn + tx * 8;
        float4 v0 = make_float4(acc[i][0], acc[i][1], acc[i][2], acc[i][3]);
        float4 v1 = make_float4(acc[i][4], acc[i][5], acc[i][6], acc[i][7]);
        *(float4*)(C + (size_t)r * N + c0)     = v0;
        *(float4*)(C + (size_t)r * N + c0 + 4) = v1;
    }
}

// ---------------- GCN aggregation ----------------
__global__ void agg_init_kernel(const float* __restrict__ h, float* __restrict__ out) {
    int idx = blockIdx.x * blockDim.x + threadIdx.x;
    if (idx >= NN * HH) return;
    int i = idx >> 8;
    float di = g_dinv[i];
    out[idx] = h[idx] * di * di;
}
__global__ void scatter_kernel(const float* __restrict__ h, const int* __restrict__ src,
                               const int* __restrict__ dst, float* __restrict__ out) {
    int e = blockIdx.x * 8 + (threadIdx.x >> 5);
    if (e >= EE) return;
    int lane = threadIdx.x & 31;
    int s = src[e], d = dst[e];
    float w = g_dinv[s] * g_dinv[d];
    const float* hp = h + (size_t)s * HH;
    float* op = out + (size_t)d * HH;
#pragma unroll
    for (int j = 0; j < 8; j++) {
        int f = lane + 32 * j;
        atomicAdd(op + f, hp[f] * w);
    }
}
__global__ void bias_relu_kernel(float* __restrict__ x, const float* __restrict__ b) {
    int idx = blockIdx.x * blockDim.x + threadIdx.x;
    if (idx >= NN * HH) return;
    x[idx] = fmaxf(x[idx] + b[idx & 255], 0.f);
}

// ---------------- pooling ----------------
__global__ void maxpool_kernel(const float* __restrict__ x, float* __restrict__ out) {
    int b = blockIdx.x, f = threadIdx.x;
    int s = g_bounds[b], e = g_bounds[b + 1];
    float m = -3.402823466e38f;
    for (int i = s; i < e; i++) m = fmaxf(m, x[(size_t)i * HH + f]);
    out[b * HH + f] = m;
}
__global__ void meanpool_kernel(const float* __restrict__ x, float* __restrict__ out) {
    int b = blockIdx.x, f = threadIdx.x;
    int s = g_bounds[b], e = g_bounds[b + 1];
    float acc = 0.f;
    for (int i = s; i < e; i++) acc += x[(size_t)i * HH + f];
    int cnt = e - s; if (cnt < 1) cnt = 1;
    out[b * HH + f] = acc / (float)cnt;
}

// ---------------- branch2: mean of raw features + root gather ----------------
__global__ void meanraw_kernel(const float* __restrict__ dx) {
    int f = blockIdx.x * 256 + threadIdx.x;
    if (f >= RAWF) return;
    int b = blockIdx.y;
    int s = g_bounds[b], e = g_bounds[b + 1];
    float acc = 0.f;
    for (int i = s; i < e; i++) acc += dx[(size_t)i * RAWF + f];
    int cnt = e - s; if (cnt < 1) cnt = 1;
    g_newxin[(size_t)b * (2 * RAWF) + f] = acc / (float)cnt;
}
__global__ void root_kernel(const float* __restrict__ dx, const int* __restrict__ root) {
    int f = blockIdx.x * 256 + threadIdx.x;
    if (f >= RAWF) return;
    int b = blockIdx.y;
    g_newxin[(size_t)b * (2 * RAWF) + RAWF + f] = dx[(size_t)root[b] * RAWF + f];
}

// ---------------- branch2 MLP ----------------
__global__ void l1_init_kernel(const float* __restrict__ bl1) {
    int idx = blockIdx.x * blockDim.x + threadIdx.x;
    if (idx < BB * 512) g_l1[idx] = bl1[idx & 511];
}
// A=[128,10000] (g_newxin), B=[10000,512] (Wl1), partial over K chunk of 400, atomicAdd into g_l1
__global__ __launch_bounds__(256)
void gemm_splitk_kernel(const float* __restrict__ B) {
    __shared__ float As[16][128];
    __shared__ float Bs[16][64];
    int tid = threadIdx.x;
    int tx = tid & 15, ty = tid >> 4;
    int n0 = blockIdx.x * 64;
    int k0 = blockIdx.y * 400;
    float acc[8][4];
#pragma unroll
    for (int i = 0; i < 8; i++)
#pragma unroll
        for (int j = 0; j < 4; j++) acc[i][j] = 0.f;

    int arow = tid >> 1;
    int acol = (tid & 1) * 8;
    int brow = tid >> 4;
    int bcoll = (tid & 15) * 4;

    for (int kt = 0; kt < 400; kt += 16) {
        const float* ap = g_newxin + (size_t)arow * (2 * RAWF) + k0 + kt + acol;
        float4 a0 = *(const float4*)ap;
        float4 a1 = *(const float4*)(ap + 4);
        As[acol + 0][arow] = a0.x; As[acol + 1][arow] = a0.y;
        As[acol + 2][arow] = a0.z; As[acol + 3][arow] = a0.w;
        As[acol + 4][arow] = a1.x; As[acol + 5][arow] = a1.y;
        As[acol + 6][arow] = a1.z; As[acol + 7][arow] = a1.w;

        float4 bv = *(const float4*)(B + (size_t)(k0 + kt + brow) * 512 + n0 + bcoll);
        Bs[brow][bcoll + 0] = bv.x; Bs[brow][bcoll + 1] = bv.y;
        Bs[brow][bcoll + 2] = bv.z; Bs[brow][bcoll + 3] = bv.w;
        __syncthreads();

#pragma unroll
        for (int kk = 0; kk < 16; kk++) {
            float a[8], b[4];
#pragma unroll
            for (int i = 0; i < 8; i++) a[i] = As[kk][ty + 16 * i];
#pragma unroll
            for (int j = 0; j < 4; j++) b[j] = Bs[kk][tx * 4 + j];
#pragma unroll
            for (int i = 0; i < 8; i++)
#pragma unroll
                for (int j = 0; j < 4; j++) acc[i][j] += a[i] * b[j];
        }
        __syncthreads();
    }
#pragma unroll
    for (int i = 0; i < 8; i++) {
        int m = ty + 16 * i;
#pragma unroll
        for (int j = 0; j < 4; j++)
            atomicAdd(&g_l1[m * 512 + n0 + tx * 4 + j], acc[i][j]);
    }
}
__global__ void prelu_l1_kernel(const float* __restrict__ pa) {
    int idx = blockIdx.x * blockDim.x + threadIdx.x;
    if (idx >= BB * 512) return;
    float a = *pa;
    float v = g_l1[idx];
    g_l1[idx] = v >= 0.f ? v : a * v;
}
__global__ void gemm_l2_kernel(const float* __restrict__ W, const float* __restrict__ bias,
                               const float* __restrict__ pa) {
    int m = blockIdx.x;      // 0..127
    int n = threadIdx.x;     // 0..255
    float acc = 0.f;
    const float* ar = g_l1 + m * 512;
    for (int k = 0; k < 512; k++) acc += ar[k] * W[k * HH + n];
    acc += bias[n];
    float a = *pa;
    g_newx[m * HH + n] = acc >= 0.f ? acc : a * acc;
}

// ---------------- final projection + log_softmax ----------------
__global__ void final_kernel(const float* __restrict__ W5, const float* __restrict__ b5,
                             float* __restrict__ out) {
    __shared__ float red[4][256];
    int b = blockIdx.x, t = threadIdx.x;
    float acc[4] = {0.f, 0.f, 0.f, 0.f};
    for (int k = t; k < 5 * HH; k += 256) {
        int seg = k >> 8, f = k & 255;
        float v;
        if      (seg == 0) v = g_p0[b * HH + f];
        else if (seg == 1) v = g_p1[b * HH + f];
        else if (seg == 2) v = g_p2[b * HH + f];
        else if (seg == 3) v = g_newx[b * HH + f];
        else               v = g_xmax[b * HH + f];
#pragma unroll
        for (int c = 0; c < 4; c++) acc[c] += v * W5[k * 4 + c];
    }
#pragma unroll
    for (int c = 0; c < 4; c++) red[c][t] = acc[c];
    __syncthreads();
    for (int s = 128; s > 0; s >>= 1) {
        if (t < s) {
#pragma unroll
            for (int c = 0; c < 4; c++) red[c][t] += red[c][t + s];
        }
        __syncthreads();
    }
    if (t == 0) {
        float z[4];
#pragma unroll
        for (int c = 0; c < 4; c++) z[c] = red[c][0] + b5[c];
        float m = z[0];
#pragma unroll
        for (int c = 1; c < 4; c++) m = fmaxf(m, z[c]);
        float ssum = 0.f;
#pragma unroll
        for (int c = 0; c < 4; c++) ssum += expf(z[c] - m);
        float ls = logf(ssum);
#pragma unroll
        for (int c = 0; c < 4; c++) out[b * 4 + c] = z[c] - m - ls;
    }
}

// ---------------- host ----------------
extern "C" void kernel_launch(void* const* d_in, const int* in_sizes, int n_in,
                              void* d_out, int out_size) {
    const float* graph_x = (const float*)d_in[0];
    // d_in[1] = bert_x (unused, bert_user=0)
    const float* data_x  = (const float*)d_in[2];
    const int*   ei      = (const int*)d_in[3];   // [2,E]: src=ei, dst=ei+EE
    const int*   rei     = (const int*)d_in[4];
    const int*   gbatch  = (const int*)d_in[5];
    // d_in[6] = x_batch (identical to graph_batch)
    const int*   root    = (const int*)d_in[7];
    const float* W1  = (const float*)d_in[8];
    const float* b1  = (const float*)d_in[9];
    const float* Wc0 = (const float*)d_in[10];
    const float* bc0 = (const float*)d_in[11];
    const float* Wc1 = (const float*)d_in[12];
    const float* bc1 = (const float*)d_in[13];
    const float* Wc2 = (const float*)d_in[14];
    const float* bc2 = (const float*)d_in[15];
    const float* Wl1 = (const float*)d_in[16];
    const float* bl1 = (const float*)d_in[17];
    const float* Wl2 = (const float*)d_in[18];
    const float* bl2 = (const float*)d_in[19];
    const float* pa  = (const float*)d_in[20];
    const float* W5  = (const float*)d_in[21];
    const float* b5  = (const float*)d_in[22];
    float* out = (float*)d_out;

    float *ph, *pagg, *pp0, *pp1, *pp2, *pxmax;
    cudaGetSymbolAddress((void**)&ph,    g_h);
    cudaGetSymbolAddress((void**)&pagg,  g_agg);
    cudaGetSymbolAddress((void**)&pp0,   g_p0);
    cudaGetSymbolAddress((void**)&pp1,   g_p1);
    cudaGetSymbolAddress((void**)&pp2,   g_p2);
    cudaGetSymbolAddress((void**)&pxmax, g_xmax);

    const int ELT = (NN * HH + 255) / 256;
    dim3 gemmGrid(2, (NN + 127) / 128);   // N=256 cols, M=20000 rows

    // segment bounds (shared by all pooling)
    bounds_kernel<<<1, 160>>>(gbatch);

    // ---------- branch 1: GCN(graph_x, W1) -> relu -> segment_max ----------
    deg_init_kernel<<<(NN + 255) / 256, 256>>>();
    deg_add_kernel<<<(EE + 255) / 256, 256>>>(ei + EE);
    dinv_kernel<<<(NN + 255) / 256, 256>>>();
    sgemm128<<<gemmGrid, 256>>>(graph_x, W1, ph, NN, HH, FIN);
    agg_init_kernel<<<ELT, 256>>>(ph, pagg);
    scatter_kernel<<<EE / 8, 256>>>(ph, ei, ei + EE, pagg);
    bias_relu_kernel<<<ELT, 256>>>(pagg, b1);
    maxpool_kernel<<<BB, HH>>>(pagg, pxmax);

    // ---------- branch 2: segment_mean(data_x) ++ root, MLP with PReLU ----------
    {
        dim3 g((RAWF + 255) / 256, BB);
        meanraw_kernel<<<g, 256>>>(data_x);
        root_kernel<<<g, 256>>>(data_x, root);
    }
    l1_init_kernel<<<(BB * 512 + 255) / 256, 256>>>(bl1);
    gemm_splitk_kernel<<<dim3(8, 25), 256>>>(Wl1);
    prelu_l1_kernel<<<(BB * 512 + 255) / 256, 256>>>(pa);
    gemm_l2_kernel<<<BB, HH>>>(Wl2, bl2, pa);

    // ---------- branch 3: 3x GCN over raw graph, mean pool each ----------
    deg_init_kernel<<<(NN + 255) / 256, 256>>>();
    deg_add_kernel<<<(EE + 255) / 256, 256>>>(rei + EE);
    dinv_kernel<<<(NN + 255) / 256, 256>>>();

    // layer 0: data_x @ Wc0
    sgemm128<<<gemmGrid, 256>>>(data_x, Wc0, ph, NN, HH, RAWF);
    agg_init_kernel<<<ELT, 256>>>(ph, pagg);
    scatter_kernel<<<EE / 8, 256>>>(ph, rei, rei + EE, pagg);
    bias_relu_kernel<<<ELT, 256>>>(pagg, bc0);
    meanpool_kernel<<<BB, HH>>>(pagg, pp0);

    // layer 1
    sgemm128<<<gemmGrid, 256>>>(pagg, Wc1, ph, NN, HH, HH);
    agg_init_kernel<<<ELT, 256>>>(ph, pagg);
    scatter_kernel<<<EE / 8, 256>>>(ph, rei, rei + EE, pagg);
    bias_relu_kernel<<<ELT, 256>>>(pagg, bc1);
    meanpool_kernel<<<BB, HH>>>(pagg, pp1);

    // layer 2
    sgemm128<<<gemmGrid, 256>>>(pagg, Wc2, ph, NN, HH, HH);
    agg_init_kernel<<<ELT, 256>>>(ph, pagg);
    scatter_kernel<<<EE / 8, 256>>>(ph, rei, rei + EE, pagg);
    bias_relu_kernel<<<ELT, 256>>>(pagg, bc2);
    meanpool_kernel<<<BB, HH>>>(pagg, pp2);

    // ---------- final: concat -> W5 -> log_softmax ----------
    final_kernel<<<BB, 256>>>(W5, b5, out);
}

// round 2
// speedup vs baseline: 4.3828x; 4.3828x over previous
#include <cuda_runtime.h>
#include <cstdint>

#define NN   20000
#define BB   128
#define EE   320000
#define FIN  768
#define RAWF 5000
#define HH   256
#define CC   4

// ---------------- scratch (device globals) ----------------
__device__ __align__(16) float g_h[NN * HH];
__device__ __align__(16) float g_agg[NN * HH];
__device__ __align__(16) float g_newxin[BB * 2 * RAWF];
__device__ __align__(16) float g_l1[BB * 512];
__device__ __align__(16) float g_newx[BB * HH];
__device__ __align__(16) float g_xmax[BB * HH];
__device__ __align__(16) float g_p0[BB * HH];
__device__ __align__(16) float g_p1[BB * HH];
__device__ __align__(16) float g_p2[BB * HH];
__device__ int   g_cnt[NN];
__device__ int   g_rowstart[NN + 1];
__device__ int   g_cursor[NN];
__device__ int   g_csrsrc[EE];
__device__ float g_dinv[NN];
__device__ int   g_bounds[BB + 1];

// ---------------- segment bounds (batch sorted) ----------------
__global__ void bounds_kernel(const int* __restrict__ batch) {
    int b = threadIdx.x;
    if (b > BB) return;
    int lo = 0, hi = NN;
    while (lo < hi) {
        int mid = (lo + hi) >> 1;
        if (batch[mid] < b) lo = mid + 1; else hi = mid;
    }
    g_bounds[b] = lo;
}

// ---------------- CSR build ----------------
__global__ void zero_cnt_kernel() {
    int i = blockIdx.x * blockDim.x + threadIdx.x;
    if (i < NN) g_cnt[i] = 0;
}
__global__ void hist_kernel(const int* __restrict__ dst) {
    int e = blockIdx.x * blockDim.x + threadIdx.x;
    if (e < EE) atomicAdd(&g_cnt[dst[e]], 1);
}
// single-block scan over 20000 counts -> rowstart, dinv
__global__ void scan_kernel() {
    __shared__ int ssum[1024];
    const int CH = 20;  // 1024*20 = 20480 >= NN
    int t = threadIdx.x;
    int base = t * CH;
    int local[CH];
    int s = 0;
    for (int i = 0; i < CH; i++) {
        int v = (base + i < NN) ? g_cnt[base + i] : 0;
        local[i] = s;
        s += v;
    }
    ssum[t] = s;
    __syncthreads();
    for (int off = 1; off < 1024; off <<= 1) {
        int v = (t >= off) ? ssum[t - off] : 0;
        __syncthreads();
        ssum[t] += v;
        __syncthreads();
    }
    int prev = (t == 0) ? 0 : ssum[t - 1];
    for (int i = 0; i < CH; i++) {
        int idx = base + i;
        if (idx < NN) {
            g_rowstart[idx] = prev + local[i];
            g_dinv[idx] = rsqrtf((float)(g_cnt[idx] + 1));
        }
    }
    if (t == 0) g_rowstart[NN] = EE;
}
__global__ void cursor_kernel() {
    int i = blockIdx.x * blockDim.x + threadIdx.x;
    if (i < NN) g_cursor[i] = g_rowstart[i];
}
__global__ void fill_kernel(const int* __restrict__ src, const int* __restrict__ dst) {
    int e = blockIdx.x * blockDim.x + threadIdx.x;
    if (e >= EE) return;
    int pos = atomicAdd(&g_cursor[dst[e]], 1);
    g_csrsrc[pos] = src[e];
}

// ---------------- fused GCN aggregation: out = relu(D^-1/2 A_hat D^-1/2 h + bias) ----------------
__global__ __launch_bounds__(256)
void gather_kernel(const float* __restrict__ h, const float* __restrict__ bias,
                   float* __restrict__ out) {
    int node = blockIdx.x * 8 + (threadIdx.x >> 5);
    if (node >= NN) return;
    int lane = threadIdx.x & 31;
    float di = g_dinv[node];
    float acc[8];
    const float* hp = h + (size_t)node * HH;
    float sw = di * di;
#pragma unroll
    for (int j = 0; j < 8; j++) acc[j] = hp[lane + 32 * j] * sw;
    int e0 = g_rowstart[node], e1 = g_rowstart[node + 1];
    for (int e = e0; e < e1; e++) {
        int s = g_csrsrc[e];
        float w = g_dinv[s] * di;
        const float* sp = h + (size_t)s * HH;
#pragma unroll
        for (int j = 0; j < 8; j++) acc[j] += sp[lane + 32 * j] * w;
    }
    float* op = out + (size_t)node * HH;
#pragma unroll
    for (int j = 0; j < 8; j++) {
        float v = acc[j] + bias[lane + 32 * j];
        op[lane + 32 * j] = fmaxf(v, 0.f);
    }
}

// ---------------- tf32 tensor-core GEMM ----------------
// C[M,N] += / = A[M,K] @ B[K,N].  CTA tile 128x256xBK32, 8 warps (2M x 4N), warp tile 64x64.
// gridDim.z splits K into chunks of KS; z>1 -> atomicAdd epilogue (C must be pre-initialized).
#define ASTR 36
#define BSTR 264
#define ASZ (128 * ASTR)
#define BSZ (32 * BSTR)
#define GSMEM ((2 * (ASZ + BSZ)) * 4)

__device__ __forceinline__ uint32_t f2tf32(float v) {
    uint32_t r;
    asm("cvt.rna.tf32.f32 %0, %1;" : "=r"(r) : "f"(v));
    return r;
}
__device__ __forceinline__ void cpasync16(uint32_t dst, const void* src, bool ok) {
    int ss = ok ? 16 : 0;
    asm volatile("cp.async.cg.shared.global [%0], [%1], 16, %2;\n" :: "r"(dst), "l"(src), "r"(ss));
}
__device__ __forceinline__ void cpcommit() { asm volatile("cp.async.commit_group;\n"); }
__device__ __forceinline__ void cpwait0()  { asm volatile("cp.async.wait_group 0;\n"); }

__global__ __launch_bounds__(256)
void gemm_tf32(const float* __restrict__ A, const float* __restrict__ B,
               float* __restrict__ C, int M, int N, int K, int KS, int atomic) {
    extern __shared__ float sm[];
    float* As = sm;                 // [2][128][ASTR]
    float* Bs = sm + 2 * ASZ;       // [2][32][BSTR]

    int tid = threadIdx.x;
    int lane = tid & 31, wid = tid >> 5;
    int warp_m = wid & 1, warp_n = wid >> 1;   // 2 x 4
    int bm = blockIdx.y * 128;
    int bn = blockIdx.x * 256;
    int kbeg = blockIdx.z * KS;
    int kend = min(K, kbeg + KS);
    int ntiles = (kend - kbeg + 31) >> 5;

    uint32_t asAddr = (uint32_t)__cvta_generic_to_shared(As);
    uint32_t bsAddr = (uint32_t)__cvta_generic_to_shared(Bs);

    float acc[4][8][4];
#pragma unroll
    for (int mt = 0; mt < 4; mt++)
#pragma unroll
        for (int nt = 0; nt < 8; nt++)
#pragma unroll
            for (int c = 0; c < 4; c++) acc[mt][nt][c] = 0.f;

    // prefetch helper (as lambda-style macro via loop body)
#define PREFETCH(TILE, BUF) do {                                                   \
    int k0 = kbeg + (TILE) * 32;                                                   \
    _Pragma("unroll")                                                              \
    for (int i = 0; i < 4; i++) {                                                  \
        int c = tid + 256 * i;                                                     \
        int row = c >> 3, seg = c & 7;                                             \
        bool ok = (bm + row < M) && (k0 + seg * 4 < kend);                          \
        const float* src = ok ? (A + (size_t)(bm + row) * K + k0 + seg * 4) : A;   \
        cpasync16(asAddr + ((BUF) * ASZ + row * ASTR + seg * 4) * 4, src, ok);     \
    }                                                                              \
    _Pragma("unroll")                                                              \
    for (int i = 0; i < 8; i++) {                                                  \
        int c = tid + 256 * i;                                                     \
        int row = c >> 6, seg = c & 63;                                            \
        bool ok = (k0 + row < kend);                                               \
        const float* src = ok ? (B + (size_t)(k0 + row) * N + bn + seg * 4) : B;   \
        cpasync16(bsAddr + ((BUF) * BSZ + row * BSTR + seg * 4) * 4, src, ok);     \
    }                                                                              \
    cpcommit();                                                                    \
} while (0)

    int buf = 0;
    PREFETCH(0, 0);

    for (int t = 0; t < ntiles; t++) {
        cpwait0();
        __syncthreads();
        if (t + 1 < ntiles) PREFETCH(t + 1, buf ^ 1);

        const float* Asb = As + buf * ASZ;
        const float* Bsb = Bs + buf * BSZ;
#pragma unroll
        for (int ks = 0; ks < 4; ks++) {
            uint32_t af[4][4];
#pragma unroll
            for (int mt = 0; mt < 4; mt++) {
                int r = warp_m * 64 + mt * 16 + (lane >> 2);
                int cc = ks * 8 + (lane & 3);
                af[mt][0] = f2tf32(Asb[r * ASTR + cc]);
                af[mt][1] = f2tf32(Asb[(r + 8) * ASTR + cc]);
                af[mt][2] = f2tf32(Asb[r * ASTR + cc + 4]);
                af[mt][3] = f2tf32(Asb[(r + 8) * ASTR + cc + 4]);
            }
            uint32_t bf[8][2];
#pragma unroll
            for (int nt = 0; nt < 8; nt++) {
                int col = warp_n * 64 + nt * 8 + (lane >> 2);
                int kr = ks * 8 + (lane & 3);
                bf[nt][0] = f2tf32(Bsb[kr * BSTR + col]);
                bf[nt][1] = f2tf32(Bsb[(kr + 4) * BSTR + col]);
            }
#pragma unroll
            for (int mt = 0; mt < 4; mt++)
#pragma unroll
                for (int nt = 0; nt < 8; nt++) {
                    asm volatile(
                        "mma.sync.aligned.m16n8k8.row.col.f32.tf32.tf32.f32 "
                        "{%0,%1,%2,%3}, {%4,%5,%6,%7}, {%8,%9}, {%0,%1,%2,%3};\n"
                        : "+f"(acc[mt][nt][0]), "+f"(acc[mt][nt][1]),
                          "+f"(acc[mt][nt][2]), "+f"(acc[mt][nt][3])
                        : "r"(af[mt][0]), "r"(af[mt][1]), "r"(af[mt][2]), "r"(af[mt][3]),
                          "r"(bf[nt][0]), "r"(bf[nt][1]));
                }
        }
        buf ^= 1;
        __syncthreads();
    }

    // epilogue
#pragma unroll
    for (int mt = 0; mt < 4; mt++) {
#pragma unroll
        for (int nt = 0; nt < 8; nt++) {
            int row = bm + warp_m * 64 + mt * 16 + (lane >> 2);
            int col = bn + warp_n * 64 + nt * 8 + 2 * (lane & 3);
            if (atomic) {
                if (row < M) {
                    atomicAdd(&C[(size_t)row * N + col],     acc[mt][nt][0]);
                    atomicAdd(&C[(size_t)row * N + col + 1], acc[mt][nt][1]);
                }
                if (row + 8 < M) {
                    atomicAdd(&C[(size_t)(row + 8) * N + col],     acc[mt][nt][2]);
                    atomicAdd(&C[(size_t)(row + 8) * N + col + 1], acc[mt][nt][3]);
                }
            } else {
                if (row < M)
                    *(float2*)&C[(size_t)row * N + col] =
                        make_float2(acc[mt][nt][0], acc[mt][nt][1]);
                if (row + 8 < M)
                    *(float2*)&C[(size_t)(row + 8) * N + col] =
                        make_float2(acc[mt][nt][2], acc[mt][nt][3]);
            }
        }
    }
#undef PREFETCH
}

// ---------------- pooling ----------------
__global__ void maxpool_kernel(const float* __restrict__ x, float* __restrict__ out) {
    int b = blockIdx.x, f = threadIdx.x;
    int s = g_bounds[b], e = g_bounds[b + 1];
    float m = -3.402823466e38f;
    for (int i = s; i < e; i++) m = fmaxf(m, x[(size_t)i * HH + f]);
    out[b * HH + f] = m;
}
__global__ void meanpool_kernel(const float* __restrict__ x, float* __restrict__ out) {
    int b = blockIdx.x, f = threadIdx.x;
    int s = g_bounds[b], e = g_bounds[b + 1];
    float acc = 0.f;
    for (int i = s; i < e; i++) acc += x[(size_t)i * HH + f];
    int cnt = e - s; if (cnt < 1) cnt = 1;
    out[b * HH + f] = acc / (float)cnt;
}

// ---------------- branch2: mean of raw features + root gather ----------------
__global__ void meanraw_kernel(const float* __restrict__ dx) {
    int f = blockIdx.x * 256 + threadIdx.x;
    if (f >= RAWF) return;
    int b = blockIdx.y;
    int s = g_bounds[b], e = g_bounds[b + 1];
    float acc = 0.f;
    for (int i = s; i < e; i++) acc += dx[(size_t)i * RAWF + f];
    int cnt = e - s; if (cnt < 1) cnt = 1;
    g_newxin[(size_t)b * (2 * RAWF) + f] = acc / (float)cnt;
}
__global__ void root_kernel(const float* __restrict__ dx, const int* __restrict__ root) {
    int f = blockIdx.x * 256 + threadIdx.x;
    if (f >= RAWF) return;
    int b = blockIdx.y;
    g_newxin[(size_t)b * (2 * RAWF) + RAWF + f] = dx[(size_t)root[b] * RAWF + f];
}

// ---------------- small elementwise ----------------
__global__ void init_bias_kernel(float* __restrict__ p, const float* __restrict__ bias,
                                 int n, int mask) {
    int i = blockIdx.x * blockDim.x + threadIdx.x;
    if (i < n) p[i] = bias[i & mask];
}
__global__ void prelu_kernel(float* __restrict__ p, int n, const float* __restrict__ pa) {
    int i = blockIdx.x * blockDim.x + threadIdx.x;
    if (i >= n) return;
    float a = *pa;
    float v = p[i];
    p[i] = v >= 0.f ? v : a * v;
}

// ---------------- final projection + log_softmax ----------------
__global__ void final_kernel(const float* __restrict__ W5, const float* __restrict__ b5,
                             float* __restrict__ out) {
    __shared__ float red[4][256];
    int b = blockIdx.x, t = threadIdx.x;
    float acc[4] = {0.f, 0.f, 0.f, 0.f};
    for (int k = t; k < 5 * HH; k += 256) {
        int seg = k >> 8, f = k & 255;
        float v;
        if      (seg == 0) v = g_p0[b * HH + f];
        else if (seg == 1) v = g_p1[b * HH + f];
        else if (seg == 2) v = g_p2[b * HH + f];
        else if (seg == 3) v = g_newx[b * HH + f];
        else               v = g_xmax[b * HH + f];
#pragma unroll
        for (int c = 0; c < 4; c++) acc[c] += v * W5[k * 4 + c];
    }
#pragma unroll
    for (int c = 0; c < 4; c++) red[c][t] = acc[c];
    __syncthreads();
    for (int s = 128; s > 0; s >>= 1) {
        if (t < s) {
#pragma unroll
            for (int c = 0; c < 4; c++) red[c][t] += red[c][t + s];
        }
        __syncthreads();
    }
    if (t == 0) {
        float z[4];
#pragma unroll
        for (int c = 0; c < 4; c++) z[c] = red[c][0] + b5[c];
        float m = z[0];
#pragma unroll
        for (int c = 1; c < 4; c++) m = fmaxf(m, z[c]);
        float ssum = 0.f;
#pragma unroll
        for (int c = 0; c < 4; c++) ssum += expf(z[c] - m);
        float ls = logf(ssum);
#pragma unroll
        for (int c = 0; c < 4; c++) out[b * 4 + c] = z[c] - m - ls;
    }
}

// ---------------- host ----------------
static void build_csr(const int* src, const int* dst) {
    zero_cnt_kernel<<<(NN + 255) / 256, 256>>>();
    hist_kernel<<<(EE + 255) / 256, 256>>>(dst);
    scan_kernel<<<1, 1024>>>();
    cursor_kernel<<<(NN + 255) / 256, 256>>>();
    fill_kernel<<<(EE + 255) / 256, 256>>>(src, dst);
}

extern "C" void kernel_launch(void* const* d_in, const int* in_sizes, int n_in,
                              void* d_out, int out_size) {
    const float* graph_x = (const float*)d_in[0];
    const float* data_x  = (const float*)d_in[2];
    const int*   ei      = (const int*)d_in[3];
    const int*   rei     = (const int*)d_in[4];
    const int*   gbatch  = (const int*)d_in[5];
    const int*   root    = (const int*)d_in[7];
    const float* W1  = (const float*)d_in[8];
    const float* b1  = (const float*)d_in[9];
    const float* Wc0 = (const float*)d_in[10];
    const float* bc0 = (const float*)d_in[11];
    const float* Wc1 = (const float*)d_in[12];
    const float* bc1 = (const float*)d_in[13];
    const float* Wc2 = (const float*)d_in[14];
    const float* bc2 = (const float*)d_in[15];
    const float* Wl1 = (const float*)d_in[16];
    const float* bl1 = (const float*)d_in[17];
    const float* Wl2 = (const float*)d_in[18];
    const float* bl2 = (const float*)d_in[19];
    const float* pa  = (const float*)d_in[20];
    const float* W5  = (const float*)d_in[21];
    const float* b5  = (const float*)d_in[22];
    float* out = (float*)d_out;

    float *ph, *pagg, *pnewxin, *pl1, *pnewx, *pxmax, *pp0, *pp1, *pp2;
    cudaGetSymbolAddress((void**)&ph,      g_h);
    cudaGetSymbolAddress((void**)&pagg,    g_agg);
    cudaGetSymbolAddress((void**)&pnewxin, g_newxin);
    cudaGetSymbolAddress((void**)&pl1,     g_l1);
    cudaGetSymbolAddress((void**)&pnewx,   g_newx);
    cudaGetSymbolAddress((void**)&pxmax,   g_xmax);
    cudaGetSymbolAddress((void**)&pp0,     g_p0);
    cudaGetSymbolAddress((void**)&pp1,     g_p1);
    cudaGetSymbolAddress((void**)&pp2,     g_p2);

    cudaFuncSetAttribute(gemm_tf32, cudaFuncAttributeMaxDynamicSharedMemorySize, GSMEM);

    dim3 nodeGrid(1, (NN + 127) / 128, 1);   // N=256 -> x=1

    bounds_kernel<<<1, 160>>>(gbatch);

    // ---------- branch 1 ----------
    build_csr(ei, ei + EE);
    gemm_tf32<<<nodeGrid, 256, GSMEM>>>(graph_x, W1, ph, NN, HH, FIN, FIN, 0);
    gather_kernel<<<NN / 8, 256>>>(ph, b1, pagg);
    maxpool_kernel<<<BB, HH>>>(pagg, pxmax);

    // ---------- branch 2 ----------
    {
        dim3 g((RAWF + 255) / 256, BB);
        meanraw_kernel<<<g, 256>>>(data_x);
        root_kernel<<<g, 256>>>(data_x, root);
    }
    init_bias_kernel<<<(BB * 512 + 255) / 256, 256>>>(pl1, bl1, BB * 512, 511);
    gemm_tf32<<<dim3(2, 1, 25), 256, GSMEM>>>(pnewxin, Wl1, pl1, BB, 512, 2 * RAWF, 416, 1);
    prelu_kernel<<<(BB * 512 + 255) / 256, 256>>>(pl1, BB * 512, pa);
    init_bias_kernel<<<(BB * 256 + 255) / 256, 256>>>(pnewx, bl2, BB * 256, 255);
    gemm_tf32<<<dim3(1, 1, 4), 256, GSMEM>>>(pl1, Wl2, pnewx, BB, HH, 512, 128, 1);
    prelu_kernel<<<(BB * 256 + 255) / 256, 256>>>(pnewx, BB * 256, pa);

    // ---------- branch 3 ----------
    build_csr(rei, rei + EE);
    gemm_tf32<<<nodeGrid, 256, GSMEM>>>(data_x, Wc0, ph, NN, HH, RAWF, RAWF, 0);
    gather_kernel<<<NN / 8, 256>>>(ph, bc0, pagg);
    meanpool_kernel<<<BB, HH>>>(pagg, pp0);

    gemm_tf32<<<nodeGrid, 256, GSMEM>>>(pagg, Wc1, ph, NN, HH, HH, HH, 0);
    gather_kernel<<<NN / 8, 256>>>(ph, bc1, pagg);
    meanpool_kernel<<<BB, HH>>>(pagg, pp1);

    gemm_tf32<<<nodeGrid, 256, GSMEM>>>(pagg, Wc2, ph, NN, HH, HH, HH, 0);
    gather_kernel<<<NN / 8, 256>>>(ph, bc2, pagg);
    meanpool_kernel<<<BB, HH>>>(pagg, pp2);

    // ---------- final ----------
    final_kernel<<<BB, 256>>>(W5, b5, out);
}

// round 3
// speedup vs baseline: 7.8319x; 1.7869x over previous
#include <cuda_runtime.h>
#include <cuda_bf16.h>
#include <cstdint>

#define NN   20000
#define BB   128
#define EE   320000
#define FIN  768
#define RAWF 5000
#define HH   256
#define CC   4

// ---------------- scratch (device globals) ----------------
__device__ __align__(16) float g_h[NN * HH];
__device__ __align__(16) float g_agg[NN * HH];
__device__ __align__(16) float g_l1[BB * 512];
__device__ __align__(16) float g_newx[BB * HH];
__device__ __align__(16) float g_xmax[BB * HH];
__device__ __align__(16) float g_p0[BB * HH];
__device__ __align__(16) float g_p1[BB * HH];
__device__ __align__(16) float g_p2[BB * HH];
__device__ __align__(16) __nv_bfloat16 g_datab[(size_t)NN * RAWF];   // bf16 data_x
__device__ __align__(16) uint32_t g_gxb[NN * FIN / 2];               // bf16 graph_x
__device__ __align__(16) __nv_bfloat16 g_newxinb[BB * 2 * RAWF];
__device__ __align__(16) __nv_bfloat16 g_l1b[BB * 512];
__device__ __align__(16) __nv_bfloat16 g_aggb[NN * HH];
// packed k2-interleaved bf16 weights
#define OFF_W1   0
#define OFF_WC0  98304
#define OFF_WC1  738304
#define OFF_WC2  771072
#define OFF_WL1  803840
#define OFF_WL2  3363840
__device__ __align__(16) uint32_t g_wp[3429376];
__device__ __align__(16) int   g_cnt[NN];
__device__ __align__(16) int   g_rowstart[NN + 4];
__device__ int   g_cursor[NN];
__device__ int   g_csrsrc[EE];
__device__ __align__(16) float g_dinv[NN];
__device__ int   g_bounds[BB + 1];

// ---------------- helpers ----------------
__device__ __forceinline__ uint32_t packbf(float lo, float hi) {
    uint32_t r;
    asm("cvt.rn.bf16x2.f32 %0, %1, %2;" : "=r"(r) : "f"(hi), "f"(lo));
    return r;
}
__device__ __forceinline__ void cpasync16(uint32_t dst, const void* src, bool ok) {
    int ss = ok ? 16 : 0;
    asm volatile("cp.async.cg.shared.global [%0], [%1], 16, %2;\n" :: "r"(dst), "l"(src), "r"(ss));
}
__device__ __forceinline__ void cpcommit() { asm volatile("cp.async.commit_group;\n"); }
__device__ __forceinline__ void cpwait0()  { asm volatile("cp.async.wait_group 0;\n"); }

// ---------------- segment bounds (batch sorted) ----------------
__global__ void bounds_kernel(const int* __restrict__ batch) {
    int b = threadIdx.x;
    if (b > BB) return;
    int lo = 0, hi = NN;
    while (lo < hi) {
        int mid = (lo + hi) >> 1;
        if (batch[mid] < b) lo = mid + 1; else hi = mid;
    }
    g_bounds[b] = lo;
}

// ---------------- conversions / weight prep ----------------
__global__ void cvt_gx_kernel(const float* __restrict__ x, int n2) {
    int i = blockIdx.x * blockDim.x + threadIdx.x;
    if (i >= n2) return;
    float2 v = ((const float2*)x)[i];
    g_gxb[i] = packbf(v.x, v.y);
}
__global__ void prep_w_kernel(const float* __restrict__ W, uint32_t* __restrict__ Wp,
                              int cnt, int N) {
    int idx = blockIdx.x * blockDim.x + threadIdx.x;
    if (idx >= cnt) return;
    int p = idx / N, n = idx - p * N;
    Wp[idx] = packbf(W[(size_t)(2 * p) * N + n], W[(size_t)(2 * p + 1) * N + n]);
}

// ---------------- CSR build ----------------
__global__ void zero_cnt_kernel() {
    int i = blockIdx.x * blockDim.x + threadIdx.x;
    if (i < NN) g_cnt[i] = 0;
}
__global__ void hist_kernel(const int* __restrict__ dst) {
    int e = blockIdx.x * blockDim.x + threadIdx.x;
    if (e < EE) atomicAdd(&g_cnt[dst[e]], 1);
}
// two-level shfl scan over 20000 counts -> rowstart, dinv
__global__ void scan_kernel() {
    __shared__ int wsum[32];
    int t = threadIdx.x;
    int lane = t & 31, wid = t >> 5;
    int c[20];
    const int4* c4 = (const int4*)g_cnt;
#pragma unroll
    for (int i = 0; i < 5; i++) {
        int idx4 = t * 5 + i;
        int4 v = (idx4 < 5000) ? c4[idx4] : make_int4(0, 0, 0, 0);
        c[i * 4 + 0] = v.x; c[i * 4 + 1] = v.y; c[i * 4 + 2] = v.z; c[i * 4 + 3] = v.w;
    }
    int loc[20];
    int s = 0;
#pragma unroll
    for (int i = 0; i < 20; i++) { loc[i] = s; s += c[i]; }
    int x = s;
#pragma unroll
    for (int off = 1; off < 32; off <<= 1) {
        int y = __shfl_up_sync(0xffffffffu, x, off);
        if (lane >= off) x += y;
    }
    if (lane == 31) wsum[wid] = x;
    __syncthreads();
    if (wid == 0) {
        int v = wsum[lane];
#pragma unroll
        for (int off = 1; off < 32; off <<= 1) {
            int y = __shfl_up_sync(0xffffffffu, v, off);
            if (lane >= off) v += y;
        }
        wsum[lane] = v;
    }
    __syncthreads();
    int offset = (wid ? wsum[wid - 1] : 0) + (x - s);
    int4* rs4 = (int4*)g_rowstart;
    float4* dv4 = (float4*)g_dinv;
#pragma unroll
    for (int i = 0; i < 5; i++) {
        int idx4 = t * 5 + i;
        if (idx4 < 5000) {
            int4 r; float4 d;
            r.x = offset + loc[i * 4 + 0]; d.x = rsqrtf((float)(c[i * 4 + 0] + 1));
            r.y = offset + loc[i * 4 + 1]; d.y = rsqrtf((float)(c[i * 4 + 1] + 1));
            r.z = offset + loc[i * 4 + 2]; d.z = rsqrtf((float)(c[i * 4 + 2] + 1));
            r.w = offset + loc[i * 4 + 3]; d.w = rsqrtf((float)(c[i * 4 + 3] + 1));
            rs4[idx4] = r; dv4[idx4] = d;
        }
    }
    if (t == 0) g_rowstart[NN] = EE;
}
__global__ void cursor_kernel() {
    int i = blockIdx.x * blockDim.x + threadIdx.x;
    if (i < NN) g_cursor[i] = g_rowstart[i];
}
__global__ void fill_kernel(const int* __restrict__ src, const int* __restrict__ dst) {
    int e = blockIdx.x * blockDim.x + threadIdx.x;
    if (e >= EE) return;
    int pos = atomicAdd(&g_cursor[dst[e]], 1);
    g_csrsrc[pos] = src[e];
}

// ---------------- fused GCN aggregation ----------------
__device__ __forceinline__ float4 fma4(float4 a, float w, float4 acc) {
    acc.x = fmaf(a.x, w, acc.x); acc.y = fmaf(a.y, w, acc.y);
    acc.z = fmaf(a.z, w, acc.z); acc.w = fmaf(a.w, w, acc.w);
    return acc;
}
__global__ __launch_bounds__(256)
void gather_kernel(const float* __restrict__ h, const float* __restrict__ bias,
                   float* __restrict__ out, __nv_bfloat16* __restrict__ outb) {
    int node = blockIdx.x * 8 + (threadIdx.x >> 5);
    int lane = threadIdx.x & 31;
    float di = g_dinv[node];
    float sw = di * di;
    const float4* hp = (const float4*)(h + (size_t)node * HH);
    float4 a0 = hp[lane], a1 = hp[lane + 32];
    float4 acc0 = make_float4(a0.x * sw, a0.y * sw, a0.z * sw, a0.w * sw);
    float4 acc1 = make_float4(a1.x * sw, a1.y * sw, a1.z * sw, a1.w * sw);
    int e0 = g_rowstart[node], e1 = g_rowstart[node + 1];
    for (int e = e0; e < e1; e++) {
        int s = g_csrsrc[e];
        float w = g_dinv[s] * di;
        const float4* sp = (const float4*)(h + (size_t)s * HH);
        acc0 = fma4(sp[lane], w, acc0);
        acc1 = fma4(sp[lane + 32], w, acc1);
    }
    const float4* bp = (const float4*)bias;
    float4 bb0 = bp[lane], bb1 = bp[lane + 32];
    float4 v0 = make_float4(fmaxf(acc0.x + bb0.x, 0.f), fmaxf(acc0.y + bb0.y, 0.f),
                            fmaxf(acc0.z + bb0.z, 0.f), fmaxf(acc0.w + bb0.w, 0.f));
    float4 v1 = make_float4(fmaxf(acc1.x + bb1.x, 0.f), fmaxf(acc1.y + bb1.y, 0.f),
                            fmaxf(acc1.z + bb1.z, 0.f), fmaxf(acc1.w + bb1.w, 0.f));
    float4* op = (float4*)(out + (size_t)node * HH);
    op[lane] = v0; op[lane + 32] = v1;
    if (outb) {
        uint2* ob = ((uint2*)outb) + (size_t)node * 64;
        ob[lane]      = make_uint2(packbf(v0.x, v0.y), packbf(v0.z, v0.w));
        ob[lane + 32] = make_uint2(packbf(v1.x, v1.y), packbf(v1.z, v1.w));
    }
}

// ---------------- bf16 tensor-core GEMM ----------------
// C[M,N] = A[M,K]@B[K,N]; A bf16 row-major, B packed k2-interleaved bf16x2 (u32[K/2][N]).
// CTA tile 160x256xk32; 8 warps as 2m x 4n, warp tile 80x64 (5 mt x 8 nt of m16n8).
// z-dim splits K in KS chunks; z>1 -> atomicAdd (pre-init C).
#define ABUF 12800            // 160*40*2 bytes per buf
#define BBUF 16896            // 16*264*4 bytes per buf
#define GSMEM (2 * (ABUF + BBUF))

__global__ __launch_bounds__(256)
void gemm_bf16(const __nv_bfloat16* __restrict__ A, const uint32_t* __restrict__ Bp,
               float* __restrict__ C, int M, int N, int K, int KS, int atomic) {
    extern __shared__ __align__(16) uint8_t smraw[];
    int tid = threadIdx.x;
    int lane = tid & 31, wid = tid >> 5;
    int warp_m = wid & 1, warp_n = wid >> 1;
    int bm = blockIdx.y * 160;
    int bn = blockIdx.x * 256;
    int kbeg = blockIdx.z * KS;
    int kend = min(K, kbeg + KS);
    int ntiles = (kend - kbeg + 31) >> 5;
    uint32_t sbase = (uint32_t)__cvta_generic_to_shared(smraw);

    float acc[5][8][4];
#pragma unroll
    for (int mt = 0; mt < 5; mt++)
#pragma unroll
        for (int nt = 0; nt < 8; nt++)
#pragma unroll
            for (int q = 0; q < 4; q++) acc[mt][nt][q] = 0.f;

#define PREFETCH(TILE, BUF) do {                                                     \
    int k0 = kbeg + (TILE) * 32;                                                     \
    _Pragma("unroll")                                                                \
    for (int i = 0; i < 3; i++) {                                                    \
        int c = tid + 256 * i;                                                       \
        if (c < 640) {                                                               \
            int row = c >> 2, chunk = c & 3;                                         \
            bool ok = (bm + row < M) && (k0 + chunk * 8 < kend);                     \
            const void* src = A + (size_t)(bm + row) * K + k0 + chunk * 8;           \
            cpasync16(sbase + (BUF) * ABUF + row * 80 + chunk * 16, ok ? src : A, ok);\
        }                                                                            \
    }                                                                                \
    _Pragma("unroll")                                                                \
    for (int i = 0; i < 4; i++) {                                                    \
        int c = tid + 256 * i;                                                       \
        int row = c >> 6, seg = c & 63;                                              \
        bool ok = (k0 + 2 * row < kend);                                             \
        const void* src = Bp + (size_t)(k0 / 2 + row) * N + bn + seg * 4;            \
        cpasync16(sbase + 2 * ABUF + (BUF) * BBUF + row * 1056 + seg * 16,           \
                  ok ? src : Bp, ok);                                                \
    }                                                                                \
    cpcommit();                                                                      \
} while (0)

    int buf = 0;
    PREFETCH(0, 0);
    for (int t = 0; t < ntiles; t++) {
        cpwait0();
        __syncthreads();
        if (t + 1 < ntiles) PREFETCH(t + 1, buf ^ 1);

        const uint16_t* Asb = (const uint16_t*)(smraw + buf * ABUF);
        const uint32_t* Bsb = (const uint32_t*)(smraw + 2 * ABUF + buf * BBUF);
#pragma unroll
        for (int ks = 0; ks < 2; ks++) {
            int kk0 = ks * 16 + 2 * (lane & 3);
            uint32_t af[5][4];
#pragma unroll
            for (int mt = 0; mt < 5; mt++) {
                int r = warp_m * 80 + mt * 16 + (lane >> 2);
                af[mt][0] = *(const uint32_t*)(Asb + r * 40 + kk0);
                af[mt][1] = *(const uint32_t*)(Asb + (r + 8) * 40 + kk0);
                af[mt][2] = *(const uint32_t*)(Asb + r * 40 + kk0 + 8);
                af[mt][3] = *(const uint32_t*)(Asb + (r + 8) * 40 + kk0 + 8);
            }
            int p = ks * 8 + (lane & 3);
#pragma unroll
            for (int nt = 0; nt < 8; nt++) {
                int cl = warp_n * 64 + nt * 8 + (lane >> 2);
                uint32_t b0 = Bsb[p * 264 + cl];
                uint32_t b1 = Bsb[(p + 4) * 264 + cl];
#pragma unroll
                for (int mt = 0; mt < 5; mt++) {
                    asm volatile(
                        "mma.sync.aligned.m16n8k16.row.col.f32.bf16.bf16.f32 "
                        "{%0,%1,%2,%3}, {%4,%5,%6,%7}, {%8,%9}, {%0,%1,%2,%3};\n"
                        : "+f"(acc[mt][nt][0]), "+f"(acc[mt][nt][1]),
                          "+f"(acc[mt][nt][2]), "+f"(acc[mt][nt][3])
                        : "r"(af[mt][0]), "r"(af[mt][1]), "r"(af[mt][2]), "r"(af[mt][3]),
                          "r"(b0), "r"(b1));
                }
            }
        }
        buf ^= 1;
        __syncthreads();
    }
#undef PREFETCH

#pragma unroll
    for (int mt = 0; mt < 5; mt++) {
#pragma unroll
        for (int nt = 0; nt < 8; nt++) {
            int row = bm + warp_m * 80 + mt * 16 + (lane >> 2);
            int col = bn + warp_n * 64 + nt * 8 + 2 * (lane & 3);
            if (atomic) {
                if (row < M) {
                    atomicAdd(&C[(size_t)row * N + col],     acc[mt][nt][0]);
                    atomicAdd(&C[(size_t)row * N + col + 1], acc[mt][nt][1]);
                }
                if (row + 8 < M) {
                    atomicAdd(&C[(size_t)(row + 8) * N + col],     acc[mt][nt][2]);
                    atomicAdd(&C[(size_t)(row + 8) * N + col + 1], acc[mt][nt][3]);
                }
            } else {
                if (row < M)
                    *(float2*)&C[(size_t)row * N + col] =
                        make_float2(acc[mt][nt][0], acc[mt][nt][1]);
                if (row + 8 < M)
                    *(float2*)&C[(size_t)(row + 8) * N + col] =
                        make_float2(acc[mt][nt][2], acc[mt][nt][3]);
            }
        }
    }
}

// ---------------- pooling ----------------
__global__ void maxpool_kernel(const float* __restrict__ x, float* __restrict__ out) {
    int b = blockIdx.x, f = threadIdx.x;
    int s = g_bounds[b], e = g_bounds[b + 1];
    float m = -3.402823466e38f;
    for (int i = s; i < e; i++) m = fmaxf(m, x[(size_t)i * HH + f]);
    out[b * HH + f] = m;
}
__global__ void meanpool_kernel(const float* __restrict__ x, float* __restrict__ out) {
    int b = blockIdx.x, f = threadIdx.x;
    int s = g_bounds[b], e = g_bounds[b + 1];
    float acc = 0.f;
    for (int i = s; i < e; i++) acc += x[(size_t)i * HH + f];
    int cnt = e - s; if (cnt < 1) cnt = 1;
    out[b * HH + f] = acc / (float)cnt;
}

// ---------------- branch2 front: mean (+ bf16 conversion of data_x) + root ----------------
__global__ void meanraw_kernel(const float* __restrict__ dx) {
    int f = blockIdx.x * 256 + threadIdx.x;
    if (f >= RAWF) return;
    int b = blockIdx.y;
    int s = g_bounds[b], e = g_bounds[b + 1];
    float acc = 0.f;
    for (int i = s; i < e; i++) {
        float v = dx[(size_t)i * RAWF + f];
        acc += v;
        g_datab[(size_t)i * RAWF + f] = __float2bfloat16(v);
    }
    int cnt = e - s; if (cnt < 1) cnt = 1;
    g_newxinb[(size_t)b * (2 * RAWF) + f] = __float2bfloat16(acc / (float)cnt);
}
__global__ void root_kernel(const float* __restrict__ dx, const int* __restrict__ root) {
    int f = blockIdx.x * 256 + threadIdx.x;
    if (f >= RAWF) return;
    int b = blockIdx.y;
    g_newxinb[(size_t)b * (2 * RAWF) + RAWF + f] =
        __float2bfloat16(dx[(size_t)root[b] * RAWF + f]);
}

// ---------------- small elementwise ----------------
__global__ void init_bias_kernel(float* __restrict__ p, const float* __restrict__ bias,
                                 int n, int mask) {
    int i = blockIdx.x * blockDim.x + threadIdx.x;
    if (i < n) p[i] = bias[i & mask];
}
__global__ void prelu_kernel(float* __restrict__ p, int n, const float* __restrict__ pa,
                             __nv_bfloat16* __restrict__ outb) {
    int i = blockIdx.x * blockDim.x + threadIdx.x;
    if (i >= n) return;
    float a = *pa;
    float v = p[i];
    v = v >= 0.f ? v : a * v;
    if (outb) outb[i] = __float2bfloat16(v);
    else p[i] = v;
}

// ---------------- final projection + log_softmax ----------------
__global__ void final_kernel(const float* __restrict__ W5, const float* __restrict__ b5,
                             float* __restrict__ out) {
    __shared__ float red[4][256];
    int b = blockIdx.x, t = threadIdx.x;
    float acc[4] = {0.f, 0.f, 0.f, 0.f};
    for (int k = t; k < 5 * HH; k += 256) {
        int seg = k >> 8, f = k & 255;
        float v;
        if      (seg == 0) v = g_p0[b * HH + f];
        else if (seg == 1) v = g_p1[b * HH + f];
        else if (seg == 2) v = g_p2[b * HH + f];
        else if (seg == 3) v = g_newx[b * HH + f];
        else               v = g_xmax[b * HH + f];
#pragma unroll
        for (int c = 0; c < 4; c++) acc[c] += v * W5[k * 4 + c];
    }
#pragma unroll
    for (int c = 0; c < 4; c++) red[c][t] = acc[c];
    __syncthreads();
    for (int s = 128; s > 0; s >>= 1) {
        if (t < s) {
#pragma unroll
            for (int c = 0; c < 4; c++) red[c][t] += red[c][t + s];
        }
        __syncthreads();
    }
    if (t == 0) {
        float z[4];
#pragma unroll
        for (int c = 0; c < 4; c++) z[c] = red[c][0] + b5[c];
        float m = z[0];
#pragma unroll
        for (int c = 1; c < 4; c++) m = fmaxf(m, z[c]);
        float ssum = 0.f;
#pragma unroll
        for (int c = 0; c < 4; c++) ssum += expf(z[c] - m);
        float ls = logf(ssum);
#pragma unroll
        for (int c = 0; c < 4; c++) out[b * 4 + c] = z[c] - m - ls;
    }
}

// ---------------- host ----------------
static void build_csr(const int* src, const int* dst) {
    zero_cnt_kernel<<<(NN + 255) / 256, 256>>>();
    hist_kernel<<<(EE + 255) / 256, 256>>>(dst);
    scan_kernel<<<1, 1024>>>();
    cursor_kernel<<<(NN + 255) / 256, 256>>>();
    fill_kernel<<<(EE + 255) / 256, 256>>>(src, dst);
}

extern "C" void kernel_launch(void* const* d_in, const int* in_sizes, int n_in,
                              void* d_out, int out_size) {
    const float* graph_x = (const float*)d_in[0];
    const float* data_x  = (const float*)d_in[2];
    const int*   ei      = (const int*)d_in[3];
    const int*   rei     = (const int*)d_in[4];
    const int*   gbatch  = (const int*)d_in[5];
    const int*   root    = (const int*)d_in[7];
    const float* W1  = (const float*)d_in[8];
    const float* b1  = (const float*)d_in[9];
    const float* Wc0 = (const float*)d_in[10];
    const float* bc0 = (const float*)d_in[11];
    const float* Wc1 = (const float*)d_in[12];
    const float* bc1 = (const float*)d_in[13];
    const float* Wc2 = (const float*)d_in[14];
    const float* bc2 = (const float*)d_in[15];
    const float* Wl1 = (const float*)d_in[16];
    const float* bl1 = (const float*)d_in[17];
    const float* Wl2 = (const float*)d_in[18];
    const float* bl2 = (const float*)d_in[19];
    const float* pa  = (const float*)d_in[20];
    const float* W5  = (const float*)d_in[21];
    const float* b5  = (const float*)d_in[22];
    float* out = (float*)d_out;

    float *ph, *pagg, *pl1, *pnewx, *pxmax, *pp0, *pp1, *pp2;
    __nv_bfloat16 *pdatab, *pnewxinb, *pl1b, *paggb;
    uint32_t *pgxb, *pwp;
    cudaGetSymbolAddress((void**)&ph,       g_h);
    cudaGetSymbolAddress((void**)&pagg,     g_agg);
    cudaGetSymbolAddress((void**)&pl1,      g_l1);
    cudaGetSymbolAddress((void**)&pnewx,    g_newx);
    cudaGetSymbolAddress((void**)&pxmax,    g_xmax);
    cudaGetSymbolAddress((void**)&pp0,      g_p0);
    cudaGetSymbolAddress((void**)&pp1,      g_p1);
    cudaGetSymbolAddress((void**)&pp2,      g_p2);
    cudaGetSymbolAddress((void**)&pdatab,   g_datab);
    cudaGetSymbolAddress((void**)&pnewxinb, g_newxinb);
    cudaGetSymbolAddress((void**)&pl1b,     g_l1b);
    cudaGetSymbolAddress((void**)&paggb,    g_aggb);
    cudaGetSymbolAddress((void**)&pgxb,     g_gxb);
    cudaGetSymbolAddress((void**)&pwp,      g_wp);

    cudaFuncSetAttribute(gemm_bf16, cudaFuncAttributeMaxDynamicSharedMemorySize, GSMEM);

    dim3 nodeGrid(1, (NN + 159) / 160, 1);   // 125 CTAs, one wave

    bounds_kernel<<<1, 160>>>(gbatch);

    // ---- prep: conversions + packed weights ----
    cvt_gx_kernel<<<(NN * FIN / 2 + 255) / 256, 256>>>(graph_x, NN * FIN / 2);
    prep_w_kernel<<<((FIN / 2) * HH + 255) / 256, 256>>>(W1,  pwp + OFF_W1,  (FIN / 2) * HH, HH);
    prep_w_kernel<<<((RAWF / 2) * HH + 255) / 256, 256>>>(Wc0, pwp + OFF_WC0, (RAWF / 2) * HH, HH);
    prep_w_kernel<<<((HH / 2) * HH + 255) / 256, 256>>>(Wc1, pwp + OFF_WC1, (HH / 2) * HH, HH);
    prep_w_kernel<<<((HH / 2) * HH + 255) / 256, 256>>>(Wc2, pwp + OFF_WC2, (HH / 2) * HH, HH);
    prep_w_kernel<<<(RAWF * 512 + 255) / 256, 256>>>(Wl1, pwp + OFF_WL1, RAWF * 512, 512);
    prep_w_kernel<<<(256 * HH + 255) / 256, 256>>>(Wl2, pwp + OFF_WL2, 256 * HH, HH);
    {
        dim3 g((RAWF + 255) / 256, BB);
        meanraw_kernel<<<g, 256>>>(data_x);   // also writes g_datab (bf16)
        root_kernel<<<g, 256>>>(data_x, root);
    }

    // ---------- branch 1 ----------
    build_csr(ei, ei + EE);
    gemm_bf16<<<nodeGrid, 256, GSMEM>>>((const __nv_bfloat16*)pgxb, pwp + OFF_W1,
                                        ph, NN, HH, FIN, FIN, 0);
    gather_kernel<<<NN / 8, 256>>>(ph, b1, pagg, nullptr);
    maxpool_kernel<<<BB, HH>>>(pagg, pxmax);

    // ---------- branch 2 ----------
    init_bias_kernel<<<(BB * 512 + 255) / 256, 256>>>(pl1, bl1, BB * 512, 511);
    gemm_bf16<<<dim3(2, 1, 63), 256, GSMEM>>>(pnewxinb, pwp + OFF_WL1,
                                              pl1, BB, 512, 2 * RAWF, 160, 1);
    prelu_kernel<<<(BB * 512 + 255) / 256, 256>>>(pl1, BB * 512, pa, pl1b);
    init_bias_kernel<<<(BB * 256 + 255) / 256, 256>>>(pnewx, bl2, BB * 256, 255);
    gemm_bf16<<<dim3(1, 1, 8), 256, GSMEM>>>(pl1b, pwp + OFF_WL2,
                                             pnewx, BB, HH, 512, 64, 1);
    prelu_kernel<<<(BB * 256 + 255) / 256, 256>>>(pnewx, BB * 256, pa, nullptr);

    // ---------- branch 3 ----------
    build_csr(rei, rei + EE);
    gemm_bf16<<<nodeGrid, 256, GSMEM>>>(pdatab, pwp + OFF_WC0, ph, NN, HH, RAWF, RAWF, 0);
    gather_kernel<<<NN / 8, 256>>>(ph, bc0, pagg, paggb);
    meanpool_kernel<<<BB, HH>>>(pagg, pp0);

    gemm_bf16<<<nodeGrid, 256, GSMEM>>>(paggb, pwp + OFF_WC1, ph, NN, HH, HH, HH, 0);
    gather_kernel<<<NN / 8, 256>>>(ph, bc1, pagg, paggb);
    meanpool_kernel<<<BB, HH>>>(pagg, pp1);

    gemm_bf16<<<nodeGrid, 256, GSMEM>>>(paggb, pwp + OFF_WC2, ph, NN, HH, HH, HH, 0);
    gather_kernel<<<NN / 8, 256>>>(ph, bc2, pagg, nullptr);
    meanpool_kernel<<<BB, HH>>>(pagg, pp2);

    // ---------- final ----------
    final_kernel<<<BB, 256>>>(W5, b5, out);
}